// round 13
// baseline (speedup 1.0000x reference)
#include <cuda_runtime.h>
#include <cstdint>

// LIF recurrence: input [B=32, T=8, C=128, H=32, W=32] fp32, output spikes same shape.
// mem = 0.5*mem + x_t; s = (mem - 1.0 > 0); mem <- mem*(1-s).
//
// FINAL — converged after 12 measured rounds. Locked config (R7):
//   45.18 / 45.54 / 45.34 / 45.25 us across four independent benches.
//   - one thread per 8 contiguous floats, 2048 blocks x 256 threads
//   - phase 1: 8x ld.global.nc.v8.f32 front-batched (8 outstanding 1KB/warp reqs)
//   - phase 2: full T=8 recurrence in registers, spikes overwrite load regs
//   - phase 3: 8x st.global.cs.v8.f32 streaming stores back-to-back
// Roofline: 268MB/replay irreducible at ~5.9 TB/s sustained mixed r/w
// (this part's read+write-turnaround HBM ceiling) => ~45us floor.
// Probed and closed: MLP/front-batch (R2), L2 read/write/pin policies
// (R3-R5), 256-bit width (R6), store policy .cs/.wt (R7/R10), persistent
// grid (R8, regression), block size (R3), global r/w phase separation
// (rejected on barrier-cost arithmetic). This kernel sits on the wall.

#define TAU  0.5f
#define V_TH 1.0f

#define CHW   131072          // 128*32*32 floats
#define CHW8  16384           // CHW/8
#define CHW8_SHIFT 14
#define CHW8_MASK  16383
#define T_STEPS 8

struct f8 { float v[8]; };

__device__ __forceinline__ f8 ldg256(const float* p) {
    f8 r;
    asm volatile("ld.global.nc.v8.f32 {%0,%1,%2,%3,%4,%5,%6,%7}, [%8];"
                 : "=f"(r.v[0]), "=f"(r.v[1]), "=f"(r.v[2]), "=f"(r.v[3]),
                   "=f"(r.v[4]), "=f"(r.v[5]), "=f"(r.v[6]), "=f"(r.v[7])
                 : "l"(p));
    return r;
}

__device__ __forceinline__ void stg256_cs(float* p, const f8& r) {
    asm volatile("st.global.cs.v8.f32 [%0], {%1,%2,%3,%4,%5,%6,%7,%8};"
                 :: "l"(p),
                    "f"(r.v[0]), "f"(r.v[1]), "f"(r.v[2]), "f"(r.v[3]),
                    "f"(r.v[4]), "f"(r.v[5]), "f"(r.v[6]), "f"(r.v[7]));
}

__global__ void __launch_bounds__(256)
lif_kernel(const float* __restrict__ x, float* __restrict__ out)
{
    int idx = blockIdx.x * blockDim.x + threadIdx.x;
    int b = idx >> CHW8_SHIFT;        // batch
    int s = idx & CHW8_MASK;          // spatial float8 index within CHW

    long base = (long)b * (T_STEPS * CHW) + (long)s * 8;
    const float* xp = x + base;
    float* op = out + base;

    // Phase 1: front-batched 256-bit loads (8 outstanding per thread).
    f8 v[T_STEPS];
    #pragma unroll
    for (int t = 0; t < T_STEPS; t++) {
        v[t] = ldg256(xp + (long)t * CHW);
    }

    // Phase 2: recurrence; spikes overwrite the load registers.
    float m[8];
    #pragma unroll
    for (int i = 0; i < 8; i++) m[i] = 0.f;

    #pragma unroll
    for (int t = 0; t < T_STEPS; t++) {
        #pragma unroll
        for (int i = 0; i < 8; i++) {
            m[i] = fmaf(TAU, m[i], v[t].v[i]);
            float s_ = (m[i] - V_TH > 0.f) ? 1.f : 0.f;
            v[t].v[i] = s_;
            m[i] = (s_ > 0.f) ? 0.f : m[i];
        }
    }

    // Phase 3: back-to-back streaming stores.
    #pragma unroll
    for (int t = 0; t < T_STEPS; t++) {
        stg256_cs(op + (long)t * CHW, v[t]);
    }
}

extern "C" void kernel_launch(void* const* d_in, const int* in_sizes, int n_in,
                              void* d_out, int out_size)
{
    const float* x = (const float*)d_in[0];
    float* out = (float*)d_out;

    const int total = 32 * CHW8;            // B * CHW/8 = 524,288 threads
    const int threads = 256;
    const int blocks = total / threads;     // 2048

    lif_kernel<<<blocks, threads>>>(x, out);
}

// round 14
// speedup vs baseline: 1.0057x; 1.0057x over previous
#include <cuda_runtime.h>
#include <cstdint>

// LIF recurrence: input [B=32, T=8, C=128, H=32, W=32] fp32, output spikes same shape.
// mem = 0.5*mem + x_t; s = (mem - 1.0 > 0); mem <- mem*(1-s).
//
// FINAL — converged. Locked config (R7), five independent benches:
//   45.18 / 45.54 / 45.34 / 45.25 / 45.34 us (mean 45.33, sigma 0.13).
//   - one thread per 8 contiguous floats, 2048 blocks x 256 threads
//   - phase 1: 8x ld.global.nc.v8.f32 front-batched (8 outstanding 1KB/warp reqs)
//   - phase 2: full T=8 recurrence in registers, spikes overwrite load regs
//   - phase 3: 8x st.global.cs.v8.f32 streaming stores back-to-back
// Roofline: 268MB/replay irreducible at ~5.9 TB/s sustained mixed r/w
// (this part's read+write-turnaround HBM ceiling) => ~45us floor.
// Closed axes: MLP/front-batch (R2), L2 read/write/pin policies (R3-R5),
// 256-bit width (R6), store policy .cs/.wt (R7/R10), persistent grid (R8,
// regression), block size (R3), global r/w phase separation (barrier-cost
// arithmetic negative), output read-compare-skip-write (violates harness
// same-work/no-caching rule). This kernel sits on the memory wall.

#define TAU  0.5f
#define V_TH 1.0f

#define CHW   131072          // 128*32*32 floats
#define CHW8  16384           // CHW/8
#define CHW8_SHIFT 14
#define CHW8_MASK  16383
#define T_STEPS 8

struct f8 { float v[8]; };

__device__ __forceinline__ f8 ldg256(const float* p) {
    f8 r;
    asm volatile("ld.global.nc.v8.f32 {%0,%1,%2,%3,%4,%5,%6,%7}, [%8];"
                 : "=f"(r.v[0]), "=f"(r.v[1]), "=f"(r.v[2]), "=f"(r.v[3]),
                   "=f"(r.v[4]), "=f"(r.v[5]), "=f"(r.v[6]), "=f"(r.v[7])
                 : "l"(p));
    return r;
}

__device__ __forceinline__ void stg256_cs(float* p, const f8& r) {
    asm volatile("st.global.cs.v8.f32 [%0], {%1,%2,%3,%4,%5,%6,%7,%8};"
                 :: "l"(p),
                    "f"(r.v[0]), "f"(r.v[1]), "f"(r.v[2]), "f"(r.v[3]),
                    "f"(r.v[4]), "f"(r.v[5]), "f"(r.v[6]), "f"(r.v[7]));
}

__global__ void __launch_bounds__(256)
lif_kernel(const float* __restrict__ x, float* __restrict__ out)
{
    int idx = blockIdx.x * blockDim.x + threadIdx.x;
    int b = idx >> CHW8_SHIFT;        // batch
    int s = idx & CHW8_MASK;          // spatial float8 index within CHW

    long base = (long)b * (T_STEPS * CHW) + (long)s * 8;
    const float* xp = x + base;
    float* op = out + base;

    // Phase 1: front-batched 256-bit loads (8 outstanding per thread).
    f8 v[T_STEPS];
    #pragma unroll
    for (int t = 0; t < T_STEPS; t++) {
        v[t] = ldg256(xp + (long)t * CHW);
    }

    // Phase 2: recurrence; spikes overwrite the load registers.
    float m[8];
    #pragma unroll
    for (int i = 0; i < 8; i++) m[i] = 0.f;

    #pragma unroll
    for (int t = 0; t < T_STEPS; t++) {
        #pragma unroll
        for (int i = 0; i < 8; i++) {
            m[i] = fmaf(TAU, m[i], v[t].v[i]);
            float s_ = (m[i] - V_TH > 0.f) ? 1.f : 0.f;
            v[t].v[i] = s_;
            m[i] = (s_ > 0.f) ? 0.f : m[i];
        }
    }

    // Phase 3: back-to-back streaming stores.
    #pragma unroll
    for (int t = 0; t < T_STEPS; t++) {
        stg256_cs(op + (long)t * CHW, v[t]);
    }
}

extern "C" void kernel_launch(void* const* d_in, const int* in_sizes, int n_in,
                              void* d_out, int out_size)
{
    const float* x = (const float*)d_in[0];
    float* out = (float*)d_out;

    const int total = 32 * CHW8;            // B * CHW/8 = 524,288 threads
    const int threads = 256;
    const int blocks = total / threads;     // 2048

    lif_kernel<<<blocks, threads>>>(x, out);
}